// round 5
// baseline (speedup 1.0000x reference)
#include <cuda_runtime.h>
#include <cstdint>

#define N_NODES 100000
#define N_EDGES 3200000
#define F_IN    300
#define HID     32
#define NCLS    10
#define H2P     12   // hidden2 padded stride (10 floats -> 12, i.e. 3 x float4)

// ---------------- scratch (device globals: no allocation allowed) ----------
__device__ int    g_is32;                 // 1 if edge_index arrived as int32
__device__ int    g_src [N_EDGES];        // 12.8 MB
__device__ int    g_dst [N_EDGES];        // 12.8 MB
__device__ float  g_deg [N_NODES];
__device__ float  g_dinv[N_NODES];
__device__ float4 g_h1  [N_NODES * (HID / 4)];   // 12.8 MB
__device__ float4 g_agg1[N_NODES * (HID / 4)];   // 12.8 MB
__device__ float4 g_h2  [N_NODES * (H2P / 4)];   // 4.8 MB
__device__ float4 g_agg2[N_NODES * (H2P / 4)];   // 4.8 MB

__device__ __forceinline__ float tanh_fast(float x) {
    float y;
    asm("tanh.approx.f32 %0, %1;" : "=f"(y) : "f"(x));
    return y;
}

__device__ __forceinline__ void red_add_v4(float4* p, float a, float b, float c, float d) {
    unsigned long long gp = __cvta_generic_to_global(p);
    asm volatile("red.global.add.v4.f32 [%0], {%1,%2,%3,%4};"
                 :: "l"(gp), "f"(a), "f"(b), "f"(c), "f"(d) : "memory");
}

// ---------------- edge-index dtype detection -------------------------------
// Reading the first 256 u64 is in-bounds under BOTH dtypes (int32 buffer is
// 2E*4B = E u64 slots). With int32 data the high word of a u64 view is
// another node index (nonzero w.p. 1-1e-5 per sample), so any v > 2^32-1
// over 256 samples => int32 essentially surely. With int64 data every value
// is a node index < 100000 => never > 2^32-1.
__global__ void k_detect(const unsigned long long* __restrict__ ei) {
    int t = threadIdx.x;
    unsigned long long v = ei[t];
    int local = (v > 0xFFFFFFFFull) ? 1 : 0;
    int any = __syncthreads_or(local);
    if (t == 0) g_is32 = any;
}

__global__ void k_initdeg() {
    int i = blockIdx.x * blockDim.x + threadIdx.x;
    if (i < N_NODES) g_deg[i] = 1.0f;   // self-loop
}

// convert indices to int32 scratch AND accumulate degree in the same pass
__global__ void k_convert_deg(const void* __restrict__ ei) {
    int e = blockIdx.x * blockDim.x + threadIdx.x;
    if (e >= N_EDGES) return;
    int s, d;
    if (g_is32) {
        const int* p = (const int*)ei;
        s = p[e];
        d = p[N_EDGES + e];
    } else {
        const long long* p = (const long long*)ei;
        s = (int)p[e];
        d = (int)p[N_EDGES + e];
    }
    g_src[e] = s;
    g_dst[e] = d;
    atomicAdd(&g_deg[d], 1.0f);
}

__global__ void k_dinv() {
    int i = blockIdx.x * blockDim.x + threadIdx.x;
    if (i < N_NODES) g_dinv[i] = rsqrtf(g_deg[i]);
}

// ---------------- layer-1 GEMM: h1 = x @ W1; agg1 = h1 * dinv^2 -----------
// block = 256 threads, 128 rows x 32 cols per block, 4x4 register tile/thread
__global__ void k_gemm1(const float* __restrict__ x, const float* __restrict__ W1) {
    __shared__ float sW[30 * 32];        // k-tile of W1
    __shared__ float sX[128 * 33];       // 128 rows x 30 k, padded stride 33

    const int tid  = threadIdx.x;
    const int row0 = blockIdx.x * 128;
    const int colg = tid & 7;            // 8 col groups of 4
    const int rowg = tid >> 3;           // 32 row groups of 4

    float acc[4][4] = {};

    for (int kt = 0; kt < 10; kt++) {
        const int k0 = kt * 30;
        for (int i = tid; i < 30 * 32; i += 256) sW[i] = W1[k0 * 32 + i];
        for (int i = tid; i < 128 * 30; i += 256) {
            int r = i / 30, c = i - r * 30;
            int row = row0 + r;
            sX[r * 33 + c] = (row < N_NODES) ? x[(size_t)row * F_IN + k0 + c] : 0.f;
        }
        __syncthreads();
        #pragma unroll
        for (int k = 0; k < 30; k++) {
            float4 w = *reinterpret_cast<const float4*>(&sW[k * 32 + colg * 4]);
            #pragma unroll
            for (int i = 0; i < 4; i++) {
                float xv = sX[(rowg * 4 + i) * 33 + k];
                acc[i][0] += xv * w.x; acc[i][1] += xv * w.y;
                acc[i][2] += xv * w.z; acc[i][3] += xv * w.w;
            }
        }
        __syncthreads();
    }

    #pragma unroll
    for (int i = 0; i < 4; i++) {
        int row = row0 + rowg * 4 + i;
        if (row < N_NODES) {
            float di  = g_dinv[row];
            float di2 = di * di;
            float4 v = make_float4(acc[i][0], acc[i][1], acc[i][2], acc[i][3]);
            g_h1  [row * 8 + colg] = v;
            g_agg1[row * 8 + colg] = make_float4(v.x * di2, v.y * di2, v.z * di2, v.w * di2);
        }
    }
}

// ---------------- layer-1 edge scatter: 8 threads / edge, float4 each -----
__global__ void k_edge1() {
    int g   = blockIdx.x * blockDim.x + threadIdx.x;   // up to 25.6M < 2^31
    int e   = g >> 3;
    int sub = g & 7;
    if (e >= N_EDGES) return;
    int src = g_src[e];
    int dst = g_dst[e];
    float norm = g_dinv[src] * g_dinv[dst];
    float4 v = g_h1[src * 8 + sub];
    red_add_v4(&g_agg1[dst * 8 + sub], v.x * norm, v.y * norm, v.z * norm, v.w * norm);
}

// ---------------- mid: h = tanh(agg1+b1); h2 = h@W2; agg2 = h2*dinv^2 -----
__global__ void k_mid(const float* __restrict__ b1, const float* __restrict__ W2) {
    __shared__ float sW2[HID * NCLS];
    __shared__ float sb1[HID];
    int tid = threadIdx.x;
    for (int i = tid; i < HID * NCLS; i += 256) sW2[i] = W2[i];
    if (tid < HID) sb1[tid] = b1[tid];
    __syncthreads();

    int n = blockIdx.x * blockDim.x + tid;
    if (n >= N_NODES) return;

    float ht[HID];
    #pragma unroll
    for (int j = 0; j < 8; j++) {
        float4 v = g_agg1[n * 8 + j];
        ht[j*4+0] = tanh_fast(v.x + sb1[j*4+0]);
        ht[j*4+1] = tanh_fast(v.y + sb1[j*4+1]);
        ht[j*4+2] = tanh_fast(v.z + sb1[j*4+2]);
        ht[j*4+3] = tanh_fast(v.w + sb1[j*4+3]);
    }

    float acc[NCLS];
    #pragma unroll
    for (int c = 0; c < NCLS; c++) acc[c] = 0.f;
    #pragma unroll
    for (int k = 0; k < HID; k++) {
        float h = ht[k];
        #pragma unroll
        for (int c = 0; c < NCLS; c++) acc[c] += h * sW2[k * NCLS + c];
    }

    float di  = g_dinv[n];
    float di2 = di * di;
    float r0[H2P];
    #pragma unroll
    for (int c = 0; c < NCLS; c++) r0[c] = acc[c];
    r0[10] = 0.f; r0[11] = 0.f;
    #pragma unroll
    for (int j = 0; j < 3; j++) {
        float4 v = make_float4(r0[j*4+0], r0[j*4+1], r0[j*4+2], r0[j*4+3]);
        g_h2[n * 3 + j] = v;
        g_agg2[n * 3 + j] = make_float4(v.x * di2, v.y * di2, v.z * di2, v.w * di2);
    }
}

// ---------------- layer-2 edge scatter: 4 threads / edge (3 active) -------
__global__ void k_edge2() {
    int g   = blockIdx.x * blockDim.x + threadIdx.x;   // up to 12.8M
    int e   = g >> 2;
    int sub = g & 3;
    if (e >= N_EDGES || sub >= 3) return;
    int src = g_src[e];
    int dst = g_dst[e];
    float norm = g_dinv[src] * g_dinv[dst];
    float4 v = g_h2[src * 3 + sub];
    red_add_v4(&g_agg2[dst * 3 + sub], v.x * norm, v.y * norm, v.z * norm, v.w * norm);
}

// ---------------- output: logits + b2 -> log_softmax ----------------------
__global__ void k_out(const float* __restrict__ b2, float* __restrict__ out) {
    __shared__ float sb2[NCLS];
    int tid = threadIdx.x;
    if (tid < NCLS) sb2[tid] = b2[tid];
    __syncthreads();
    int n = blockIdx.x * blockDim.x + tid;
    if (n >= N_NODES) return;

    const float* a = reinterpret_cast<const float*>(&g_agg2[n * 3]);
    float v[NCLS];
    #pragma unroll
    for (int c = 0; c < NCLS; c++) v[c] = a[c] + sb2[c];
    float m = v[0];
    #pragma unroll
    for (int c = 1; c < NCLS; c++) m = fmaxf(m, v[c]);
    float s = 0.f;
    #pragma unroll
    for (int c = 0; c < NCLS; c++) s += expf(v[c] - m);
    float ls = logf(s) + m;
    #pragma unroll
    for (int c = 0; c < NCLS; c++) out[(size_t)n * NCLS + c] = v[c] - ls;
}

// ---------------- launch ---------------------------------------------------
extern "C" void kernel_launch(void* const* d_in, const int* in_sizes, int n_in,
                              void* d_out, int out_size) {
    const float* x  = (const float*)d_in[0];
    const void*  ei = d_in[1];
    const float* W1 = (const float*)d_in[2];
    const float* b1 = (const float*)d_in[3];
    const float* W2 = (const float*)d_in[4];
    const float* b2 = (const float*)d_in[5];
    float*       out = (float*)d_out;

    k_detect     <<<1, 256>>>((const unsigned long long*)ei);
    k_initdeg    <<<(N_NODES + 255) / 256, 256>>>();
    k_convert_deg<<<(N_EDGES + 255) / 256, 256>>>(ei);
    k_dinv       <<<(N_NODES + 255) / 256, 256>>>();
    k_gemm1      <<<(N_NODES + 127) / 128, 256>>>(x, W1);
    k_edge1      <<<(N_EDGES * 8) / 256, 256>>>();        // exactly 100000 blocks
    k_mid        <<<(N_NODES + 255) / 256, 256>>>(b1, W2);
    k_edge2      <<<(N_EDGES * 4) / 256, 256>>>();        // exactly 50000 blocks
    k_out        <<<(N_NODES + 255) / 256, 256>>>(b2, out);
}

// round 6
// speedup vs baseline: 1.0286x; 1.0286x over previous
#include <cuda_runtime.h>
#include <cstdint>

#define N_NODES 100000
#define N_EDGES 3200000
#define F_IN    300
#define HID     32
#define NCLS    10
#define H2P     12    // hidden2 padded row: 10 -> 12 floats (3 x float4)

#define SCAN_B  512
#define SCAN_NBLK ((N_NODES + SCAN_B - 1) / SCAN_B)   // 196

// ---------------- scratch (device globals: no allocation allowed) ----------
__device__ int    g_is32;
__device__ int    g_ecnt[N_NODES];        // edge count per dst (no self-loop)
__device__ int    g_off [N_NODES];        // CSR offsets (exclusive scan of ecnt)
__device__ int    g_cur [N_NODES];        // fill cursors
__device__ int    g_bsum[SCAN_NBLK];
__device__ int    g_bpre[SCAN_NBLK];
__device__ float  g_dinv[N_NODES];
__device__ int2   g_csr [N_EDGES];        // {src, norm-as-int} 25.6 MB
__device__ float4 g_h1  [N_NODES * (HID / 4)];   // 12.8 MB
__device__ float4 g_agg1[N_NODES * (HID / 4)];   // 12.8 MB
__device__ float4 g_h2  [N_NODES * (H2P / 4)];   // 4.8 MB
__device__ float4 g_agg2[N_NODES * (H2P / 4)];   // 4.8 MB

__device__ __forceinline__ float tanh_fast(float x) {
    float y;
    asm("tanh.approx.f32 %0, %1;" : "=f"(y) : "f"(x));
    return y;
}

// ---------------- edge-index dtype detection -------------------------------
// First 256 u64 reads are in-bounds under both dtypes (int32 buffer = E u64
// slots). int32 data: high word of a u64 view is another node index, nonzero
// w.p. 1-1e-5 per sample -> any v > 2^32-1 over 256 samples => int32.
__global__ void k_detect(const unsigned long long* __restrict__ ei) {
    int t = threadIdx.x;
    unsigned long long v = ei[t];
    int any = __syncthreads_or(v > 0xFFFFFFFFull ? 1 : 0);
    if (t == 0) g_is32 = any;
}

__global__ void k_zero() {
    int i = blockIdx.x * blockDim.x + threadIdx.x;
    if (i < N_NODES) g_ecnt[i] = 0;
}

__global__ void k_hist(const void* __restrict__ ei) {
    int e = blockIdx.x * blockDim.x + threadIdx.x;   // grid covers exactly E
    int d = g_is32 ? ((const int*)ei)[N_EDGES + e]
                   : (int)((const long long*)ei)[N_EDGES + e];
    atomicAdd(&g_ecnt[d], 1);
}

// ---------------- 3-kernel exclusive scan of g_ecnt ------------------------
__global__ void k_scan_reduce() {
    __shared__ int s[SCAN_B];
    int i = blockIdx.x * SCAN_B + threadIdx.x;
    s[threadIdx.x] = (i < N_NODES) ? g_ecnt[i] : 0;
    __syncthreads();
    for (int d = SCAN_B / 2; d > 0; d >>= 1) {
        if (threadIdx.x < d) s[threadIdx.x] += s[threadIdx.x + d];
        __syncthreads();
    }
    if (threadIdx.x == 0) g_bsum[blockIdx.x] = s[0];
}

__global__ void k_scan_mid() {
    int run = 0;
    for (int b = 0; b < SCAN_NBLK; b++) { g_bpre[b] = run; run += g_bsum[b]; }
}

// writes offsets + cursor copy, and fuses dinv = rsqrt(ecnt + 1 self-loop)
__global__ void k_scan_write() {
    __shared__ int s[SCAN_B];
    int t = threadIdx.x;
    int i = blockIdx.x * SCAN_B + t;
    int v = (i < N_NODES) ? g_ecnt[i] : 0;
    s[t] = v;
    __syncthreads();
    for (int d = 1; d < SCAN_B; d <<= 1) {
        int add = (t >= d) ? s[t - d] : 0;
        __syncthreads();
        s[t] += add;
        __syncthreads();
    }
    if (i < N_NODES) {
        int off = g_bpre[blockIdx.x] + s[t] - v;   // exclusive
        g_off[i] = off;
        g_cur[i] = off;
        g_dinv[i] = rsqrtf((float)(v + 1));
    }
}

// ---------------- CSR fill: {src, norm} per slot ---------------------------
__global__ void k_fill(const void* __restrict__ ei) {
    int e = blockIdx.x * blockDim.x + threadIdx.x;
    int s, d;
    if (g_is32) {
        const int* p = (const int*)ei;
        s = p[e]; d = p[N_EDGES + e];
    } else {
        const long long* p = (const long long*)ei;
        s = (int)p[e]; d = (int)p[N_EDGES + e];
    }
    float nrm = g_dinv[s] * g_dinv[d];
    int slot = atomicAdd(&g_cur[d], 1);
    g_csr[slot] = make_int2(s, __float_as_int(nrm));
}

// ---------------- layer-1 GEMM: h1 = x @ W1 --------------------------------
__global__ void k_gemm1(const float* __restrict__ x, const float* __restrict__ W1) {
    __shared__ float sW[30 * 32];
    __shared__ float sX[128 * 33];

    const int tid  = threadIdx.x;
    const int row0 = blockIdx.x * 128;
    const int colg = tid & 7;
    const int rowg = tid >> 3;

    float acc[4][4] = {};

    for (int kt = 0; kt < 10; kt++) {
        const int k0 = kt * 30;
        for (int i = tid; i < 30 * 32; i += 256) sW[i] = W1[k0 * 32 + i];
        for (int i = tid; i < 128 * 30; i += 256) {
            int r = i / 30, c = i - r * 30;
            int row = row0 + r;
            sX[r * 33 + c] = (row < N_NODES) ? x[(size_t)row * F_IN + k0 + c] : 0.f;
        }
        __syncthreads();
        #pragma unroll
        for (int k = 0; k < 30; k++) {
            float4 w = *reinterpret_cast<const float4*>(&sW[k * 32 + colg * 4]);
            #pragma unroll
            for (int i = 0; i < 4; i++) {
                float xv = sX[(rowg * 4 + i) * 33 + k];
                acc[i][0] += xv * w.x; acc[i][1] += xv * w.y;
                acc[i][2] += xv * w.z; acc[i][3] += xv * w.w;
            }
        }
        __syncthreads();
    }

    #pragma unroll
    for (int i = 0; i < 4; i++) {
        int row = row0 + rowg * 4 + i;
        if (row < N_NODES)
            g_h1[row * 8 + colg] = make_float4(acc[i][0], acc[i][1], acc[i][2], acc[i][3]);
    }
}

// ---------------- layer-1 aggregation: one warp per node -------------------
// lane = nb*8 + sub : nb in [0,4) = neighbor slot, sub in [0,8) = float4 col
__global__ void k_agg1() {
    int w = (blockIdx.x * blockDim.x + threadIdx.x) >> 5;  // node (exactly 100000 warps)
    int lane = threadIdx.x & 31;
    int sub  = lane & 7;
    int nb   = lane >> 3;

    int   off = g_off[w];
    int   cnt = g_ecnt[w];
    float di  = g_dinv[w];
    float di2 = di * di;

    float4 acc = make_float4(0.f, 0.f, 0.f, 0.f);
    if (nb == 0) {                       // self-loop term
        float4 h = g_h1[w * 8 + sub];
        acc = make_float4(h.x * di2, h.y * di2, h.z * di2, h.w * di2);
    }

    for (int i = nb; i < cnt; i += 4) {
        int2  sn  = g_csr[off + i];
        float nrm = __int_as_float(sn.y);
        float4 v  = g_h1[sn.x * 8 + sub];
        acc.x += v.x * nrm; acc.y += v.y * nrm;
        acc.z += v.z * nrm; acc.w += v.w * nrm;
    }

    // reduce over nb groups (lanes differ in bits 3,4)
    #pragma unroll
    for (int m = 8; m <= 16; m <<= 1) {
        acc.x += __shfl_xor_sync(0xFFFFFFFFu, acc.x, m);
        acc.y += __shfl_xor_sync(0xFFFFFFFFu, acc.y, m);
        acc.z += __shfl_xor_sync(0xFFFFFFFFu, acc.z, m);
        acc.w += __shfl_xor_sync(0xFFFFFFFFu, acc.w, m);
    }
    if (nb == 0) g_agg1[w * 8 + sub] = acc;
}

// ---------------- mid: h = tanh(agg1+b1); h2 = h @ W2 ----------------------
__global__ void k_mid(const float* __restrict__ b1, const float* __restrict__ W2) {
    __shared__ float sW2[HID * NCLS];
    __shared__ float sb1[HID];
    int tid = threadIdx.x;
    for (int i = tid; i < HID * NCLS; i += 256) sW2[i] = W2[i];
    if (tid < HID) sb1[tid] = b1[tid];
    __syncthreads();

    int n = blockIdx.x * blockDim.x + tid;
    if (n >= N_NODES) return;

    float ht[HID];
    #pragma unroll
    for (int j = 0; j < 8; j++) {
        float4 v = g_agg1[n * 8 + j];
        ht[j*4+0] = tanh_fast(v.x + sb1[j*4+0]);
        ht[j*4+1] = tanh_fast(v.y + sb1[j*4+1]);
        ht[j*4+2] = tanh_fast(v.z + sb1[j*4+2]);
        ht[j*4+3] = tanh_fast(v.w + sb1[j*4+3]);
    }

    float acc[NCLS];
    #pragma unroll
    for (int c = 0; c < NCLS; c++) acc[c] = 0.f;
    #pragma unroll
    for (int k = 0; k < HID; k++) {
        float h = ht[k];
        #pragma unroll
        for (int c = 0; c < NCLS; c++) acc[c] += h * sW2[k * NCLS + c];
    }

    float r0[H2P];
    #pragma unroll
    for (int c = 0; c < NCLS; c++) r0[c] = acc[c];
    r0[10] = 0.f; r0[11] = 0.f;
    #pragma unroll
    for (int j = 0; j < 3; j++)
        g_h2[n * 3 + j] = make_float4(r0[j*4+0], r0[j*4+1], r0[j*4+2], r0[j*4+3]);
}

// ---------------- layer-2 aggregation: one warp per node -------------------
// lane = sub*8 + nb : sub in [0,4) (sub 3 idle/clamped), nb in [0,8)
__global__ void k_agg2() {
    int w = (blockIdx.x * blockDim.x + threadIdx.x) >> 5;
    int lane = threadIdx.x & 31;
    int nb   = lane & 7;
    int sub  = lane >> 3;
    int csub = (sub < 3) ? sub : 2;      // clamp lanes 24-31 to a safe address

    int   off = g_off[w];
    int   cnt = g_ecnt[w];
    float di  = g_dinv[w];
    float di2 = di * di;

    float4 acc = make_float4(0.f, 0.f, 0.f, 0.f);
    if (nb == 0 && sub < 3) {            // self-loop term
        float4 h = g_h2[w * 3 + sub];
        acc = make_float4(h.x * di2, h.y * di2, h.z * di2, h.w * di2);
    }

    for (int i = nb; i < cnt; i += 8) {
        int2  sn  = g_csr[off + i];
        float nrm = __int_as_float(sn.y);
        float4 v  = g_h2[sn.x * 3 + csub];
        acc.x += v.x * nrm; acc.y += v.y * nrm;
        acc.z += v.z * nrm; acc.w += v.w * nrm;
    }

    // reduce over nb (bits 0-2); sub groups stay disjoint
    #pragma unroll
    for (int m = 1; m <= 4; m <<= 1) {
        acc.x += __shfl_xor_sync(0xFFFFFFFFu, acc.x, m);
        acc.y += __shfl_xor_sync(0xFFFFFFFFu, acc.y, m);
        acc.z += __shfl_xor_sync(0xFFFFFFFFu, acc.z, m);
        acc.w += __shfl_xor_sync(0xFFFFFFFFu, acc.w, m);
    }
    if (nb == 0 && sub < 3) g_agg2[w * 3 + sub] = acc;
}

// ---------------- output: logits + b2 -> log_softmax -----------------------
__global__ void k_out(const float* __restrict__ b2, float* __restrict__ out) {
    __shared__ float sb2[NCLS];
    int tid = threadIdx.x;
    if (tid < NCLS) sb2[tid] = b2[tid];
    __syncthreads();
    int n = blockIdx.x * blockDim.x + tid;
    if (n >= N_NODES) return;

    const float* a = reinterpret_cast<const float*>(&g_agg2[n * 3]);
    float v[NCLS];
    #pragma unroll
    for (int c = 0; c < NCLS; c++) v[c] = a[c] + sb2[c];
    float m = v[0];
    #pragma unroll
    for (int c = 1; c < NCLS; c++) m = fmaxf(m, v[c]);
    float s = 0.f;
    #pragma unroll
    for (int c = 0; c < NCLS; c++) s += expf(v[c] - m);
    float ls = logf(s) + m;
    #pragma unroll
    for (int c = 0; c < NCLS; c++) out[(size_t)n * NCLS + c] = v[c] - ls;
}

// ---------------- launch ---------------------------------------------------
extern "C" void kernel_launch(void* const* d_in, const int* in_sizes, int n_in,
                              void* d_out, int out_size) {
    const float* x  = (const float*)d_in[0];
    const void*  ei = d_in[1];
    const float* W1 = (const float*)d_in[2];
    const float* b1 = (const float*)d_in[3];
    const float* W2 = (const float*)d_in[4];
    const float* b2 = (const float*)d_in[5];
    float*       out = (float*)d_out;

    k_detect     <<<1, 256>>>((const unsigned long long*)ei);
    k_zero       <<<(N_NODES + 255) / 256, 256>>>();
    k_hist       <<<N_EDGES / 256, 256>>>(ei);           // 12500 blocks, exact
    k_scan_reduce<<<SCAN_NBLK, SCAN_B>>>();
    k_scan_mid   <<<1, 1>>>();
    k_scan_write <<<SCAN_NBLK, SCAN_B>>>();
    k_fill       <<<N_EDGES / 256, 256>>>(ei);
    k_gemm1      <<<(N_NODES + 127) / 128, 256>>>(x, W1);
    k_agg1       <<<N_NODES * 32 / 256, 256>>>();        // 12500 blocks, 1 warp/node
    k_mid        <<<(N_NODES + 255) / 256, 256>>>(b1, W2);
    k_agg2       <<<N_NODES * 32 / 256, 256>>>();
    k_out        <<<(N_NODES + 255) / 256, 256>>>(b2, out);
}